// round 2
// baseline (speedup 1.0000x reference)
#include <cuda_runtime.h>
#include <cuda_bf16.h>
#include <math.h>

// Problem constants
#define BATCH 2
#define SEQ   2048
#define SIZE  1024
#define HEADS 16
#define HDIM  64
#define M_TOK (BATCH * SEQ)          // 4096 token rows
#define BH    (BATCH * HEADS)        // 32 batch-heads

// -------- scratch (device globals; no allocations allowed) --------
__device__ float g_q[(size_t)BH * SEQ * HDIM];       // 16 MB  [B,H,S,D]
__device__ float g_k[(size_t)BH * SEQ * HDIM];
__device__ float g_v[(size_t)BH * SEQ * HDIM];
__device__ float g_oh[(size_t)BH * SEQ * HDIM];      // attn @ V result, head layout
__device__ float g_attn_scratch[(size_t)BH * SEQ * SEQ]; // 512 MB, used only if attn not in d_out
__device__ float g_out_scratch[(size_t)M_TOK * SIZE];    // used only if out not in d_out

// ==================================================================
// GEMM: Y = X @ W^T + bias   (M=4096, N=1024, K=1024)
// IN_MODE:  0 = X row-major [M,K];   1 = gather X from [B,H,S,D] head layout
// OUT_MODE: 0 = Y row-major [M,N];   1 = scatter Y to [B,H,S,D] head layout
// Tile 128x128x16, 256 threads, 8x8 per-thread micro-tile, float4 smem reads.
// ==================================================================
template<int IN_MODE, int OUT_MODE>
__global__ void __launch_bounds__(256) gemm4096(const float* __restrict__ X,
                                                const float* __restrict__ W,
                                                const float* __restrict__ bias,
                                                float* __restrict__ Y) {
    const int K = 1024, N = 1024;
    __shared__ __align__(16) float As[16][128];
    __shared__ __align__(16) float Bs[16][128];
    const int bm = blockIdx.y, bn = blockIdx.x;
    const int tid = threadIdx.x;
    const int tx = tid & 15, ty = tid >> 4;

    float acc[8][8];
    #pragma unroll
    for (int i = 0; i < 8; i++)
        #pragma unroll
        for (int j = 0; j < 8; j++) acc[i][j] = 0.f;

    for (int kt = 0; kt < K; kt += 16) {
        // A tile: rows bm*128+i, cols kt+j  (2 float4 per thread)
        #pragma unroll
        for (int l = 0; l < 2; l++) {
            int v = tid * 2 + l;          // 0..511
            int i = v >> 2;               // 0..127
            int j = (v & 3) * 4;          // 0,4,8,12
            int gm = bm * 128 + i;
            int gk = kt + j;
            float4 t;
            if (IN_MODE == 0) {
                t = *reinterpret_cast<const float4*>(X + (size_t)gm * K + gk);
            } else {
                int b = gm >> 11, s = gm & 2047;
                int h = gk >> 6, d = gk & 63;
                t = *reinterpret_cast<const float4*>(
                    X + ((((size_t)b * HEADS + h) * SEQ + s) << 6) + d);
            }
            As[j + 0][i] = t.x; As[j + 1][i] = t.y;
            As[j + 2][i] = t.z; As[j + 3][i] = t.w;
        }
        // B tile: W row-major [N,K], rows bn*128+i, cols kt+j
        #pragma unroll
        for (int l = 0; l < 2; l++) {
            int v = tid * 2 + l;
            int i = v >> 2;
            int j = (v & 3) * 4;
            float4 t = *reinterpret_cast<const float4*>(
                W + (size_t)(bn * 128 + i) * K + kt + j);
            Bs[j + 0][i] = t.x; Bs[j + 1][i] = t.y;
            Bs[j + 2][i] = t.z; Bs[j + 3][i] = t.w;
        }
        __syncthreads();
        #pragma unroll
        for (int kk = 0; kk < 16; kk++) {
            const float4* ar = reinterpret_cast<const float4*>(&As[kk][ty * 8]);
            const float4* br = reinterpret_cast<const float4*>(&Bs[kk][tx * 8]);
            float4 a0 = ar[0], a1 = ar[1];
            float4 b0 = br[0], b1 = br[1];
            float a[8] = {a0.x, a0.y, a0.z, a0.w, a1.x, a1.y, a1.z, a1.w};
            float b[8] = {b0.x, b0.y, b0.z, b0.w, b1.x, b1.y, b1.z, b1.w};
            #pragma unroll
            for (int i = 0; i < 8; i++)
                #pragma unroll
                for (int j = 0; j < 8; j++) acc[i][j] += a[i] * b[j];
        }
        __syncthreads();
    }

    #pragma unroll
    for (int i = 0; i < 8; i++) {
        int gm = bm * 128 + ty * 8 + i;
        #pragma unroll
        for (int j = 0; j < 8; j++) {
            int gn = bn * 128 + tx * 8 + j;
            float val = acc[i][j] + bias[gn];
            if (OUT_MODE == 0) {
                Y[(size_t)gm * N + gn] = val;
            } else {
                int b = gm >> 11, s = gm & 2047;
                int h = gn >> 6, d = gn & 63;
                Y[((((size_t)b * HEADS + h) * SEQ + s) << 6) + d] = val;
            }
        }
    }
}

// ==================================================================
// Scores: attn_raw[bh,q,k] = (1/8) * sum_d Q[bh,q,d]*K[bh,k,d]
// Only lower-triangular tiles computed (bn <= bm). 128x128 tiles, K=64.
// ==================================================================
__global__ void __launch_bounds__(256) scores_kernel(const float* __restrict__ Q,
                                                     const float* __restrict__ Kh,
                                                     float* __restrict__ attn) {
    const int bm = blockIdx.y, bn = blockIdx.x, bh = blockIdx.z;
    if (bn > bm) return;
    const float* q = Q + (size_t)bh * SEQ * HDIM;
    const float* k = Kh + (size_t)bh * SEQ * HDIM;
    float* out = attn + (size_t)bh * SEQ * SEQ;

    __shared__ __align__(16) float As[16][128];
    __shared__ __align__(16) float Bs[16][128];
    const int tid = threadIdx.x;
    const int tx = tid & 15, ty = tid >> 4;

    float acc[8][8];
    #pragma unroll
    for (int i = 0; i < 8; i++)
        #pragma unroll
        for (int j = 0; j < 8; j++) acc[i][j] = 0.f;

    for (int kt = 0; kt < HDIM; kt += 16) {
        #pragma unroll
        for (int l = 0; l < 2; l++) {
            int v = tid * 2 + l;
            int i = v >> 2;
            int j = (v & 3) * 4;
            float4 t = *reinterpret_cast<const float4*>(
                q + (size_t)(bm * 128 + i) * HDIM + kt + j);
            As[j + 0][i] = t.x; As[j + 1][i] = t.y;
            As[j + 2][i] = t.z; As[j + 3][i] = t.w;
        }
        #pragma unroll
        for (int l = 0; l < 2; l++) {
            int v = tid * 2 + l;
            int i = v >> 2;
            int j = (v & 3) * 4;
            float4 t = *reinterpret_cast<const float4*>(
                k + (size_t)(bn * 128 + i) * HDIM + kt + j);
            Bs[j + 0][i] = t.x; Bs[j + 1][i] = t.y;
            Bs[j + 2][i] = t.z; Bs[j + 3][i] = t.w;
        }
        __syncthreads();
        #pragma unroll
        for (int kk = 0; kk < 16; kk++) {
            const float4* ar = reinterpret_cast<const float4*>(&As[kk][ty * 8]);
            const float4* br = reinterpret_cast<const float4*>(&Bs[kk][tx * 8]);
            float4 a0 = ar[0], a1 = ar[1];
            float4 b0 = br[0], b1 = br[1];
            float a[8] = {a0.x, a0.y, a0.z, a0.w, a1.x, a1.y, a1.z, a1.w};
            float b[8] = {b0.x, b0.y, b0.z, b0.w, b1.x, b1.y, b1.z, b1.w};
            #pragma unroll
            for (int i = 0; i < 8; i++)
                #pragma unroll
                for (int j = 0; j < 8; j++) acc[i][j] += a[i] * b[j];
        }
        __syncthreads();
    }

    const float scale = 0.125f;   // 1/sqrt(64)
    #pragma unroll
    for (int i = 0; i < 8; i++) {
        int gq = bm * 128 + ty * 8 + i;
        #pragma unroll
        for (int j = 0; j < 8; j++) {
            int gk = bn * 128 + tx * 8 + j;
            out[(size_t)gq * SEQ + gk] = acc[i][j] * scale;
        }
    }
}

// ==================================================================
// Causal softmax, in-place. One block per (bh, q) row.
// Writes the FULL row: normalized for k<=q, exact 0 for k>q.
// ==================================================================
__global__ void __launch_bounds__(256) softmax_kernel(float* __restrict__ attn) {
    const int row = blockIdx.x;         // 0 .. BH*SEQ-1
    const int q = row & (SEQ - 1);
    float* p = attn + (size_t)row * SEQ;
    const int tid = threadIdx.x;
    const int n = q + 1;

    __shared__ float red[256];

    float m = -INFINITY;
    for (int i = tid; i < n; i += 256) m = fmaxf(m, p[i]);
    red[tid] = m; __syncthreads();
    for (int s = 128; s > 0; s >>= 1) {
        if (tid < s) red[tid] = fmaxf(red[tid], red[tid + s]);
        __syncthreads();
    }
    m = red[0];
    __syncthreads();

    float sum = 0.f;
    for (int i = tid; i < n; i += 256) sum += __expf(p[i] - m);
    red[tid] = sum; __syncthreads();
    for (int s = 128; s > 0; s >>= 1) {
        if (tid < s) red[tid] += red[tid + s];
        __syncthreads();
    }
    const float inv = 1.0f / red[0];
    __syncthreads();

    for (int i = tid; i < SEQ; i += 256) {
        float v = (i < n) ? __expf(p[i] - m) * inv : 0.0f;
        p[i] = v;
    }
}

// ==================================================================
// attn @ V : Oh[bh,q,d] = sum_k attn[bh,q,k]*V[bh,k,d]
// 64x64 output tile per block (full N=64), BK=32, K-loop truncated at
// the causal boundary. 4x4 micro-tile, 256 threads.
// ==================================================================
__global__ void __launch_bounds__(256) attnv_kernel(const float* __restrict__ attn,
                                                    const float* __restrict__ V,
                                                    float* __restrict__ Oh) {
    const int qt = blockIdx.x, bh = blockIdx.y;
    const float* a = attn + (size_t)bh * SEQ * SEQ;
    const float* v = V + (size_t)bh * SEQ * HDIM;
    float* o = Oh + (size_t)bh * SEQ * HDIM;

    __shared__ __align__(16) float As[32][68];   // As[k][m] (transposed, 16B-aligned rows)
    __shared__ __align__(16) float Vs[32][64];   // Vs[k][d]
    const int tid = threadIdx.x;
    const int tx = tid & 15, ty = tid >> 4;

    float acc[4][4];
    #pragma unroll
    for (int i = 0; i < 4; i++)
        #pragma unroll
        for (int j = 0; j < 4; j++) acc[i][j] = 0.f;

    const int nkt = 2 * qt + 2;   // K tiles covering k <= qt*64+63
    for (int kt = 0; kt < nkt; kt++) {
        #pragma unroll
        for (int l = 0; l < 2; l++) {
            int vv = tid * 2 + l;        // 0..511
            int i = vv >> 3;             // row 0..63
            int j = (vv & 7) * 4;        // 0..28
            float4 t = *reinterpret_cast<const float4*>(
                a + (size_t)(qt * 64 + i) * SEQ + kt * 32 + j);
            As[j + 0][i] = t.x; As[j + 1][i] = t.y;
            As[j + 2][i] = t.z; As[j + 3][i] = t.w;
        }
        #pragma unroll
        for (int l = 0; l < 2; l++) {
            int vv = tid * 2 + l;
            int i = vv >> 4;             // k 0..31
            int j = (vv & 15) * 4;       // d 0..60
            float4 t = *reinterpret_cast<const float4*>(
                v + (size_t)(kt * 32 + i) * HDIM + j);
            Vs[i][j + 0] = t.x; Vs[i][j + 1] = t.y;
            Vs[i][j + 2] = t.z; Vs[i][j + 3] = t.w;
        }
        __syncthreads();
        #pragma unroll
        for (int kk = 0; kk < 32; kk++) {
            float4 av = *reinterpret_cast<const float4*>(&As[kk][ty * 4]);
            float4 bv = *reinterpret_cast<const float4*>(&Vs[kk][tx * 4]);
            float aa[4] = {av.x, av.y, av.z, av.w};
            float bb[4] = {bv.x, bv.y, bv.z, bv.w};
            #pragma unroll
            for (int i = 0; i < 4; i++)
                #pragma unroll
                for (int j = 0; j < 4; j++) acc[i][j] += aa[i] * bb[j];
        }
        __syncthreads();
    }

    #pragma unroll
    for (int i = 0; i < 4; i++) {
        int gq = qt * 64 + ty * 4 + i;
        #pragma unroll
        for (int j = 0; j < 4; j++) {
            o[(size_t)gq * HDIM + tx * 4 + j] = acc[i][j];
        }
    }
}

// ==================================================================
// host launcher
// ==================================================================
extern "C" void kernel_launch(void* const* d_in, const int* in_sizes, int n_in,
                              void* d_out, int out_size) {
    const float* key   = (const float*)d_in[0];
    const float* value = (const float*)d_in[1];
    const float* query = (const float*)d_in[2];
    // d_in[3] = mask (causal, known statically; unused)
    const float* Wk = (const float*)d_in[4];
    const float* bk = (const float*)d_in[5];
    const float* Wv = (const float*)d_in[6];
    const float* bv = (const float*)d_in[7];
    const float* Wq = (const float*)d_in[8];
    const float* bq = (const float*)d_in[9];
    const float* Wo = (const float*)d_in[10];
    const float* bo = (const float*)d_in[11];

    float *qh, *kh, *vh, *oh, *attn_scr, *out_scr;
    cudaGetSymbolAddress((void**)&qh, g_q);
    cudaGetSymbolAddress((void**)&kh, g_k);
    cudaGetSymbolAddress((void**)&vh, g_v);
    cudaGetSymbolAddress((void**)&oh, g_oh);
    cudaGetSymbolAddress((void**)&attn_scr, g_attn_scratch);
    cudaGetSymbolAddress((void**)&out_scr, g_out_scratch);

    const long long OUT_ELE  = (long long)M_TOK * SIZE;          // 4,194,304
    const long long ATTN_ELE = (long long)BH * SEQ * SEQ;        // 134,217,728

    float* dout = (float*)d_out;
    float* outp;
    float* attnp;
    if ((long long)out_size >= OUT_ELE + ATTN_ELE) {
        outp = dout;                  // tuple flattened: out first, then attn
        attnp = dout + OUT_ELE;
    } else if ((long long)out_size == ATTN_ELE) {
        attnp = dout;                 // only attn checked
        outp = out_scr;
    } else {
        outp = dout;                  // only out checked
        attnp = attn_scr;
    }

    dim3 gThr(256);
    dim3 gGemm(SIZE / 128, M_TOK / 128);           // (8, 32)

    // 1) projections -> head layout [B,H,S,D]
    gemm4096<0, 1><<<gGemm, gThr>>>(query, Wq, bq, qh);
    gemm4096<0, 1><<<gGemm, gThr>>>(key,   Wk, bk, kh);
    gemm4096<0, 1><<<gGemm, gThr>>>(value, Wv, bv, vh);

    // 2) causal scores (lower-triangular tiles only)
    dim3 gScores(SEQ / 128, SEQ / 128, BH);        // (16, 16, 32)
    scores_kernel<<<gScores, gThr>>>(qh, kh, attnp);

    // 3) softmax rows (writes every attn element, zeros above diagonal)
    softmax_kernel<<<BH * SEQ, gThr>>>(attnp);

    // 4) attn @ V (causally truncated K loop)
    dim3 gAV(SEQ / 64, BH);                        // (32, 32)
    attnv_kernel<<<gAV, gThr>>>(attnp, vh, oh);

    // 5) output projection (gather from head layout)
    gemm4096<1, 0><<<gGemm, gThr>>>(oh, Wo, bo, outp);
}

// round 4
// speedup vs baseline: 1.7605x; 1.7605x over previous
#include <cuda_runtime.h>
#include <mma.h>
#include <cstdint>
#include <math.h>

using namespace nvcuda;

// Problem constants
#define BATCH 2
#define SEQ   2048
#define SIZE  1024
#define HEADS 16
#define HDIM  64
#define M_TOK (BATCH * SEQ)
#define BH    (BATCH * HEADS)

// -------- scratch (device globals; no allocations allowed) --------
__device__ float g_q[(size_t)BH * SEQ * HDIM];        // [bh, s, d]
__device__ float g_k[(size_t)BH * SEQ * HDIM];        // [bh, s, d]
__device__ float g_v[(size_t)BH * SEQ * HDIM];        // [bh, s, d]
__device__ float g_oh[(size_t)BH * SEQ * HDIM];       // [bh, s, d]
__device__ float g_attn_scratch[(size_t)BH * SEQ * SEQ];
__device__ float g_out_scratch[(size_t)M_TOK * SIZE];

__device__ __forceinline__ float f2tf32f(float x) {
    uint32_t r;
    asm("cvt.rna.tf32.f32 %0, %1;" : "=r"(r) : "f"(x));
    return __uint_as_float(r);
}

// fragment typedefs
typedef wmma::fragment<wmma::matrix_a, 16, 16, 8, wmma::precision::tf32, wmma::row_major> FragA;
typedef wmma::fragment<wmma::matrix_b, 16, 16, 8, wmma::precision::tf32, wmma::col_major> FragBc;
typedef wmma::fragment<wmma::matrix_b, 16, 16, 8, wmma::precision::tf32, wmma::row_major> FragBr;
typedef wmma::fragment<wmma::accumulator, 16, 16, 8, float> FragC;

#define LDA 36   // smem leading dim for 32-wide K tiles (pad 4)
#define LDV 68   // smem leading dim for 64-wide V tiles (pad 4)

// ==================================================================
// Projection GEMM: Y = X @ W^T + bias.  M=4096, N=1024, K=1024.
// IN_MODE: 0 = row-major X[M,1024]; 1 = gather from head layout [bh,s,d]
// OUT_MODE: 0 = row-major Y[M,1024]; 1 = head layout [bh,s,d]
// CTA 128x128, BK=32, 8 warps (2m x 4n), warp tile 64x32.
// ==================================================================
template<int IN_MODE, int OUT_MODE>
__global__ void __launch_bounds__(256) proj_wmma(const float* __restrict__ X,
                                                 const float* __restrict__ W,
                                                 const float* __restrict__ bias,
                                                 float* __restrict__ Y) {
    __shared__ __align__(16) float As[128 * LDA];
    __shared__ __align__(16) float Bs[128 * LDA];
    __shared__ __align__(16) float stage[8][272];

    const int tid = threadIdx.x, wid = tid >> 5, lane = tid & 31;
    const int bm = blockIdx.y, bn = blockIdx.x;
    const int wm0 = (wid & 1) * 64, wn0 = (wid >> 1) * 32;

    FragC acc[4][2];
    #pragma unroll
    for (int mt = 0; mt < 4; mt++)
        #pragma unroll
        for (int nt = 0; nt < 2; nt++) wmma::fill_fragment(acc[mt][nt], 0.0f);

    for (int kc = 0; kc < 1024; kc += 32) {
        // load A 128x32, B 128x32 (4 float4 per thread each)
        #pragma unroll
        for (int l = 0; l < 4; l++) {
            int v = tid + l * 256;
            int i = v >> 3;
            int j = (v & 7) * 4;
            float4 t;
            if (IN_MODE == 0) {
                t = *reinterpret_cast<const float4*>(
                    X + (size_t)(bm * 128 + i) * 1024 + kc + j);
            } else {
                int gm = bm * 128 + i;
                int b = gm >> 11, s = gm & 2047;
                int h = kc >> 6, d0 = kc & 63;     // 32-chunk stays in one head
                t = *reinterpret_cast<const float4*>(
                    X + ((((size_t)b * HEADS + h) * SEQ + s) << 6) + d0 + j);
            }
            float4 u = {f2tf32f(t.x), f2tf32f(t.y), f2tf32f(t.z), f2tf32f(t.w)};
            *reinterpret_cast<float4*>(&As[i * LDA + j]) = u;
            float4 w = *reinterpret_cast<const float4*>(
                W + (size_t)(bn * 128 + i) * 1024 + kc + j);
            float4 uw = {f2tf32f(w.x), f2tf32f(w.y), f2tf32f(w.z), f2tf32f(w.w)};
            *reinterpret_cast<float4*>(&Bs[i * LDA + j]) = uw;
        }
        __syncthreads();

        #pragma unroll
        for (int ks = 0; ks < 32; ks += 8) {
            FragA af[4];
            FragBc bf[2];
            #pragma unroll
            for (int mt = 0; mt < 4; mt++)
                wmma::load_matrix_sync(af[mt], &As[(wm0 + mt * 16) * LDA + ks], LDA);
            #pragma unroll
            for (int nt = 0; nt < 2; nt++)
                wmma::load_matrix_sync(bf[nt], &Bs[(wn0 + nt * 16) * LDA + ks], LDA);
            #pragma unroll
            for (int mt = 0; mt < 4; mt++)
                #pragma unroll
                for (int nt = 0; nt < 2; nt++)
                    wmma::mma_sync(acc[mt][nt], af[mt], bf[nt], acc[mt][nt]);
        }
        __syncthreads();
    }

    // epilogue via per-warp staging
    #pragma unroll
    for (int mt = 0; mt < 4; mt++) {
        #pragma unroll
        for (int nt = 0; nt < 2; nt++) {
            wmma::store_matrix_sync(&stage[wid][0], acc[mt][nt], 16, wmma::mem_row_major);
            __syncwarp();
            int r = lane >> 1, c8 = (lane & 1) * 8;
            int gm = bm * 128 + wm0 + mt * 16 + r;
            int gn_t = bn * 128 + wn0 + nt * 16;
            float out[8];
            #pragma unroll
            for (int jj = 0; jj < 8; jj++)
                out[jj] = stage[wid][r * 16 + c8 + jj] + bias[gn_t + c8 + jj];
            float* dst;
            if (OUT_MODE == 0) {
                dst = Y + (size_t)gm * SIZE + gn_t + c8;
            } else {
                int b = gm >> 11, s = gm & 2047;
                int h = gn_t >> 6, d0 = (gn_t & 63) + c8;
                dst = Y + ((((size_t)b * HEADS + h) * SEQ + s) << 6) + d0;
            }
            *reinterpret_cast<float4*>(dst)     = make_float4(out[0], out[1], out[2], out[3]);
            *reinterpret_cast<float4*>(dst + 4) = make_float4(out[4], out[5], out[6], out[7]);
            __syncwarp();
        }
    }
}

// ==================================================================
// Scores: attn[bh,q,k] = (Q @ K^T)/8, lower-triangular 128x128 tiles.
// ==================================================================
__global__ void __launch_bounds__(256) scores_wmma(const float* __restrict__ Q,
                                                   const float* __restrict__ Kh,
                                                   float* __restrict__ attn) {
    const int bn = blockIdx.x, bm = blockIdx.y, bh = blockIdx.z;
    if (bn > bm) return;
    __shared__ __align__(16) float As[128 * LDA];
    __shared__ __align__(16) float Bs[128 * LDA];
    __shared__ __align__(16) float stage[8][272];

    const int tid = threadIdx.x, wid = tid >> 5, lane = tid & 31;
    const int wm0 = (wid & 1) * 64, wn0 = (wid >> 1) * 32;
    const float* q = Q + (size_t)bh * SEQ * HDIM;
    const float* k = Kh + (size_t)bh * SEQ * HDIM;

    FragC acc[4][2];
    #pragma unroll
    for (int mt = 0; mt < 4; mt++)
        #pragma unroll
        for (int nt = 0; nt < 2; nt++) wmma::fill_fragment(acc[mt][nt], 0.0f);

    for (int kc = 0; kc < HDIM; kc += 32) {
        #pragma unroll
        for (int l = 0; l < 4; l++) {
            int v = tid + l * 256;
            int i = v >> 3;
            int j = (v & 7) * 4;
            float4 t = *reinterpret_cast<const float4*>(
                q + (size_t)(bm * 128 + i) * HDIM + kc + j);
            float4 u = {f2tf32f(t.x), f2tf32f(t.y), f2tf32f(t.z), f2tf32f(t.w)};
            *reinterpret_cast<float4*>(&As[i * LDA + j]) = u;
            float4 w = *reinterpret_cast<const float4*>(
                k + (size_t)(bn * 128 + i) * HDIM + kc + j);
            float4 uw = {f2tf32f(w.x), f2tf32f(w.y), f2tf32f(w.z), f2tf32f(w.w)};
            *reinterpret_cast<float4*>(&Bs[i * LDA + j]) = uw;
        }
        __syncthreads();

        #pragma unroll
        for (int ks = 0; ks < 32; ks += 8) {
            FragA af[4];
            FragBc bf[2];
            #pragma unroll
            for (int mt = 0; mt < 4; mt++)
                wmma::load_matrix_sync(af[mt], &As[(wm0 + mt * 16) * LDA + ks], LDA);
            #pragma unroll
            for (int nt = 0; nt < 2; nt++)
                wmma::load_matrix_sync(bf[nt], &Bs[(wn0 + nt * 16) * LDA + ks], LDA);
            #pragma unroll
            for (int mt = 0; mt < 4; mt++)
                #pragma unroll
                for (int nt = 0; nt < 2; nt++)
                    wmma::mma_sync(acc[mt][nt], af[mt], bf[nt], acc[mt][nt]);
        }
        __syncthreads();
    }

    #pragma unroll
    for (int mt = 0; mt < 4; mt++) {
        #pragma unroll
        for (int nt = 0; nt < 2; nt++) {
            wmma::store_matrix_sync(&stage[wid][0], acc[mt][nt], 16, wmma::mem_row_major);
            __syncwarp();
            int r = lane >> 1, c8 = (lane & 1) * 8;
            int gq = bm * 128 + wm0 + mt * 16 + r;
            int gk0 = bn * 128 + wn0 + nt * 16 + c8;
            float out[8];
            #pragma unroll
            for (int jj = 0; jj < 8; jj++)
                out[jj] = stage[wid][r * 16 + c8 + jj] * 0.125f;
            float* dst = attn + ((size_t)bh * SEQ + gq) * SEQ + gk0;
            *reinterpret_cast<float4*>(dst)     = make_float4(out[0], out[1], out[2], out[3]);
            *reinterpret_cast<float4*>(dst + 4) = make_float4(out[4], out[5], out[6], out[7]);
            __syncwarp();
        }
    }
}

// ==================================================================
// Causal softmax, 1 read + 1 write, smem row cache. Block per row.
// ==================================================================
__global__ void __launch_bounds__(256) softmax_kernel(float* __restrict__ attn) {
    __shared__ __align__(16) float sbuf[SEQ];
    __shared__ float red[8];
    const int row = blockIdx.x;
    const int qi = row & (SEQ - 1);
    const int n = qi + 1;
    const int n4 = (n + 3) >> 2;
    float* p = attn + (size_t)row * SEQ;
    const int tid = threadIdx.x, wid = tid >> 5, lane = tid & 31;

    float m = -INFINITY;
    for (int i4 = tid; i4 < n4; i4 += 256) {
        float4 t = reinterpret_cast<const float4*>(p)[i4];
        int base = i4 * 4;
        t.x = (base + 0 < n) ? t.x : -INFINITY;
        t.y = (base + 1 < n) ? t.y : -INFINITY;
        t.z = (base + 2 < n) ? t.z : -INFINITY;
        t.w = (base + 3 < n) ? t.w : -INFINITY;
        reinterpret_cast<float4*>(sbuf)[i4] = t;
        m = fmaxf(m, fmaxf(fmaxf(t.x, t.y), fmaxf(t.z, t.w)));
    }
    #pragma unroll
    for (int o = 16; o; o >>= 1) m = fmaxf(m, __shfl_xor_sync(~0u, m, o));
    if (lane == 0) red[wid] = m;
    __syncthreads();
    m = red[0];
    #pragma unroll
    for (int w = 1; w < 8; w++) m = fmaxf(m, red[w]);
    __syncthreads();

    float sum = 0.f;
    for (int i4 = tid; i4 < n4; i4 += 256) {
        float4 t = reinterpret_cast<const float4*>(sbuf)[i4];
        t.x = __expf(t.x - m); t.y = __expf(t.y - m);
        t.z = __expf(t.z - m); t.w = __expf(t.w - m);
        reinterpret_cast<float4*>(sbuf)[i4] = t;
        sum += t.x + t.y + t.z + t.w;
    }
    #pragma unroll
    for (int o = 16; o; o >>= 1) sum += __shfl_xor_sync(~0u, sum, o);
    if (lane == 0) red[wid] = sum;
    __syncthreads();
    sum = red[0];
    #pragma unroll
    for (int w = 1; w < 8; w++) sum += red[w];
    const float inv = 1.0f / sum;
    __syncthreads();

    for (int i4 = tid; i4 < SEQ / 4; i4 += 256) {
        float4 o = {0.f, 0.f, 0.f, 0.f};
        if (i4 < n4) {
            float4 t = reinterpret_cast<const float4*>(sbuf)[i4];
            o.x = t.x * inv; o.y = t.y * inv; o.z = t.z * inv; o.w = t.w * inv;
        }
        reinterpret_cast<float4*>(p)[i4] = o;
    }
}

// ==================================================================
// attn @ V : Oh[bh,q,d] = sum_k attn[bh,q,k] * V[bh,k,d]
// CTA 128(q) x 64(d), BK=32, K truncated at causal boundary.
// 8 warps (4m x 2n), warp tile 32x32 (2x2 frags). V is matrix_b row_major.
// ==================================================================
__global__ void __launch_bounds__(256) attnv_wmma(const float* __restrict__ attn,
                                                  const float* __restrict__ V,
                                                  float* __restrict__ Oh) {
    const int qt = blockIdx.x, bh = blockIdx.y;
    __shared__ __align__(16) float As[128 * LDA];
    __shared__ __align__(16) float Vs[32 * LDV];
    __shared__ __align__(16) float stage[8][272];

    const int tid = threadIdx.x, wid = tid >> 5, lane = tid & 31;
    const int wm0 = (wid & 3) * 32, wn0 = (wid >> 2) * 32;
    const float* a = attn + (size_t)bh * SEQ * SEQ;
    const float* v = V + (size_t)bh * SEQ * HDIM;

    FragC acc[2][2];
    #pragma unroll
    for (int mt = 0; mt < 2; mt++)
        #pragma unroll
        for (int nt = 0; nt < 2; nt++) wmma::fill_fragment(acc[mt][nt], 0.0f);

    const int kend = (qt + 1) * 128;   // causal truncation
    for (int kc = 0; kc < kend; kc += 32) {
        #pragma unroll
        for (int l = 0; l < 4; l++) {
            int vv = tid + l * 256;
            int i = vv >> 3;
            int j = (vv & 7) * 4;
            float4 t = *reinterpret_cast<const float4*>(
                a + (size_t)(qt * 128 + i) * SEQ + kc + j);
            float4 u = {f2tf32f(t.x), f2tf32f(t.y), f2tf32f(t.z), f2tf32f(t.w)};
            *reinterpret_cast<float4*>(&As[i * LDA + j]) = u;
        }
        #pragma unroll
        for (int l = 0; l < 2; l++) {
            int vv = tid + l * 256;         // 0..511
            int i = vv >> 4;                // k row 0..31
            int j = (vv & 15) * 4;          // d 0..60
            float4 t = *reinterpret_cast<const float4*>(
                v + (size_t)(kc + i) * HDIM + j);
            float4 u = {f2tf32f(t.x), f2tf32f(t.y), f2tf32f(t.z), f2tf32f(t.w)};
            *reinterpret_cast<float4*>(&Vs[i * LDV + j]) = u;
        }
        __syncthreads();

        #pragma unroll
        for (int ks = 0; ks < 32; ks += 8) {
            FragA af[2];
            FragBr bf[2];
            #pragma unroll
            for (int mt = 0; mt < 2; mt++)
                wmma::load_matrix_sync(af[mt], &As[(wm0 + mt * 16) * LDA + ks], LDA);
            #pragma unroll
            for (int nt = 0; nt < 2; nt++)
                wmma::load_matrix_sync(bf[nt], &Vs[ks * LDV + wn0 + nt * 16], LDV);
            #pragma unroll
            for (int mt = 0; mt < 2; mt++)
                #pragma unroll
                for (int nt = 0; nt < 2; nt++)
                    wmma::mma_sync(acc[mt][nt], af[mt], bf[nt], acc[mt][nt]);
        }
        __syncthreads();
    }

    #pragma unroll
    for (int mt = 0; mt < 2; mt++) {
        #pragma unroll
        for (int nt = 0; nt < 2; nt++) {
            wmma::store_matrix_sync(&stage[wid][0], acc[mt][nt], 16, wmma::mem_row_major);
            __syncwarp();
            int r = lane >> 1, c8 = (lane & 1) * 8;
            int gq = qt * 128 + wm0 + mt * 16 + r;
            int d0 = wn0 + nt * 16 + c8;
            float out[8];
            #pragma unroll
            for (int jj = 0; jj < 8; jj++)
                out[jj] = stage[wid][r * 16 + c8 + jj];
            float* dst = Oh + (((size_t)bh * SEQ + gq) << 6) + d0;
            *reinterpret_cast<float4*>(dst)     = make_float4(out[0], out[1], out[2], out[3]);
            *reinterpret_cast<float4*>(dst + 4) = make_float4(out[4], out[5], out[6], out[7]);
            __syncwarp();
        }
    }
}

// ==================================================================
// host launcher
// ==================================================================
extern "C" void kernel_launch(void* const* d_in, const int* in_sizes, int n_in,
                              void* d_out, int out_size) {
    const float* key   = (const float*)d_in[0];
    const float* value = (const float*)d_in[1];
    const float* query = (const float*)d_in[2];
    const float* Wk = (const float*)d_in[4];
    const float* bk = (const float*)d_in[5];
    const float* Wv = (const float*)d_in[6];
    const float* bv = (const float*)d_in[7];
    const float* Wq = (const float*)d_in[8];
    const float* bq = (const float*)d_in[9];
    const float* Wo = (const float*)d_in[10];
    const float* bo = (const float*)d_in[11];

    float *qh, *kh, *vh, *oh, *attn_scr, *out_scr;
    cudaGetSymbolAddress((void**)&qh, g_q);
    cudaGetSymbolAddress((void**)&kh, g_k);
    cudaGetSymbolAddress((void**)&vh, g_v);
    cudaGetSymbolAddress((void**)&oh, g_oh);
    cudaGetSymbolAddress((void**)&attn_scr, g_attn_scratch);
    cudaGetSymbolAddress((void**)&out_scr, g_out_scratch);

    const long long OUT_ELE  = (long long)M_TOK * SIZE;
    const long long ATTN_ELE = (long long)BH * SEQ * SEQ;

    float* dout = (float*)d_out;
    float* outp;
    float* attnp;
    if ((long long)out_size >= OUT_ELE + ATTN_ELE) {
        outp = dout; attnp = dout + OUT_ELE;
    } else if ((long long)out_size == ATTN_ELE) {
        attnp = dout; outp = out_scr;
    } else {
        outp = dout; attnp = attn_scr;
    }

    dim3 thr(256);
    dim3 gProj(SIZE / 128, M_TOK / 128);           // (8, 32)

    proj_wmma<0, 1><<<gProj, thr>>>(query, Wq, bq, qh);
    proj_wmma<0, 1><<<gProj, thr>>>(key,   Wk, bk, kh);
    proj_wmma<0, 1><<<gProj, thr>>>(value, Wv, bv, vh);

    dim3 gScores(SEQ / 128, SEQ / 128, BH);        // (16, 16, 32)
    scores_wmma<<<gScores, thr>>>(qh, kh, attnp);

    softmax_kernel<<<BH * SEQ, thr>>>(attnp);

    dim3 gAV(SEQ / 128, BH);                       // (16, 32)
    attnv_wmma<<<gAV, thr>>>(attnp, vh, oh);

    proj_wmma<1, 0><<<gProj, thr>>>(oh, Wo, bo, outp);
}